// round 16
// baseline (speedup 1.0000x reference)
#include <cuda_runtime.h>
#include <cuda_fp16.h>
#include <cstdint>

// ============================================================================
// y[8192,4096] = x[8192,4096] @ sign(W)[4096,4096], fp32 in/out.
// Plain-sm_103 target (no tcgen05). Pipelined HMMA GEMM, 2 CTAs/SM,
// CTA tile 128x128, warp tile 64x64, bulk-DMA stages from pre-swizzled blobs,
// mbarrier ring. R16 (from R14 best): DEDICATED producer warp (160 threads;
// warps 0-3 pure ldsm+mma, warp 4 only manages the ring) — removes DMA issue
// + empty-barrier waits from the MMA critical path (R15 profile: HMMA floor
// is 455us; R14 ran at 87.6%). Conversions merged into one launch.
// ============================================================================

#define MM 8192
#define NN 4096
#define KK 4096

#define TM 128
#define TN 128
#define TK 64
#define NSTAGE 3
#define NK (KK / TK)               // 64

#define BLOB_BYTES 16384           // one 128x64 fp16 tile, swizzled
#define BLOB_ELEMS 8192
#define STAGE_BYTES (2 * BLOB_BYTES)
#define SMEM_TILES_OFF 1024
#define SMEM_TOTAL (SMEM_TILES_OFF + NSTAGE * STAGE_BYTES)   // 99328 -> 2 CTAs/SM

#define NTHREADS 160               // 4 consumer warps + 1 producer warp
#define NBLOBS_A ((MM / 128) * (KK / 64))   // 4096
#define NBLOBS_B ((NN / 128) * (KK / 64))   // 2048

__device__ __align__(1024) __half g_xh[(size_t)MM * KK];   // A blobs
__device__ __align__(1024) __half g_sh[(size_t)NN * KK];   // B blobs

// ---------------------------------------------------------------------------
__device__ __forceinline__ uint32_t smem_u32(const void* p) {
    uint32_t a;
    asm("{ .reg .u64 t; cvta.to.shared.u64 t, %1; cvt.u32.u64 %0, t; }"
        : "=r"(a) : "l"(p));
    return a;
}
__device__ __forceinline__ uint32_t h2_u32(__half2 h) {
    return reinterpret_cast<uint32_t&>(h);
}

#define MBARRIER_INIT(addr, count) \
    asm volatile("mbarrier.init.shared.b64 [%0], %1;" \
        :: "r"((uint32_t)(addr)), "r"((uint32_t)(count)) : "memory")
#define MBARRIER_EXPECT_TX(addr, bytes) \
    asm volatile("mbarrier.arrive.expect_tx.shared.b64 _, [%0], %1;" \
        :: "r"((uint32_t)(addr)), "r"((uint32_t)(bytes)) : "memory")
#define MBARRIER_ARRIVE(addr) \
    asm volatile("mbarrier.arrive.shared.b64 _, [%0];" \
        :: "r"((uint32_t)(addr)) : "memory")
#define MBARRIER_WAIT_PARITY(mbar_smem_addr, phase_parity) do { \
    uint32_t _mbar = (uint32_t)(mbar_smem_addr); \
    uint32_t _parity = (uint32_t)(phase_parity); \
    uint32_t _done; \
    asm volatile( \
        "{\n\t.reg .pred p;\n\t" \
        "mbarrier.try_wait.parity.acquire.cta.shared::cta.b64 p, [%1], %2;\n\t" \
        "selp.b32 %0, 1, 0, p;\n\t}" \
        : "=r"(_done) : "r"(_mbar), "r"(_parity) : "memory"); \
    if (!_done) { \
        asm volatile( \
            "{\n\t.reg .pred P1;\n\t" \
            "WAIT_LOOP_%=:\n\t" \
            "mbarrier.try_wait.parity.acquire.cta.shared::cta.b64 P1, [%0], %1, 0x989680;\n\t" \
            "@P1 bra.uni WAIT_DONE_%=;\n\t" \
            "bra.uni WAIT_LOOP_%=;\n\t" \
            "WAIT_DONE_%=:\n\t}" \
            :: "r"(_mbar), "r"(_parity) : "memory"); \
    } \
} while (0)
#define FENCE_PROXY_ASYNC() \
    asm volatile("fence.proxy.async.shared::cta;" ::: "memory")
#define CP_BULK(dst, src, bytes, mbar) \
    asm volatile( \
        "cp.async.bulk.shared::cluster.global.mbarrier::complete_tx::bytes " \
        "[%0], [%1], %2, [%3];" \
        :: "r"((uint32_t)(dst)), "l"(src), "r"((uint32_t)(bytes)), \
           "r"((uint32_t)(mbar)) : "memory")

__device__ __forceinline__ void ldsm4(uint32_t* r, uint32_t addr) {
    asm volatile("ldmatrix.sync.aligned.m8n8.x4.shared.b16 {%0,%1,%2,%3}, [%4];"
        : "=r"(r[0]), "=r"(r[1]), "=r"(r[2]), "=r"(r[3]) : "r"(addr));
}
__device__ __forceinline__ void mma16816(float* c, const uint32_t* a, const uint32_t* b) {
    asm volatile(
        "mma.sync.aligned.m16n8k16.row.col.f32.f16.f16.f32 "
        "{%0,%1,%2,%3}, {%4,%5,%6,%7}, {%8,%9}, {%0,%1,%2,%3};"
        : "+f"(c[0]), "+f"(c[1]), "+f"(c[2]), "+f"(c[3])
        : "r"(a[0]), "r"(a[1]), "r"(a[2]), "r"(a[3]), "r"(b[0]), "r"(b[1]));
}

// ---------------------------------------------------------------------------
// Merged conversion kernel. Block b < NBLOBS_A: A blob (tm = b>>6, ks = b&63);
// else B blob (tn, ks) of sign(W)^T via 64x128 smem transpose.
// Blob layout: 128 rows x 128B, chunk c of row r stored at r*128 + (c^(r&7))*16.
// ---------------------------------------------------------------------------
__global__ void k_conv(const float* __restrict__ x, const float* __restrict__ W) {
    __shared__ float t[64][129];
    int b = blockIdx.x;
    int tid = threadIdx.x;
    if (b < NBLOBS_A) {
        int tm = b >> 6, ks = b & 63;
        const float* src = x + (size_t)tm * 128 * KK + ks * 64;
        char* dst = reinterpret_cast<char*>(g_xh + (size_t)b * BLOB_ELEMS);
#pragma unroll
        for (int i = 0; i < 4; ++i) {          // 1024 chunks / 256 threads
            int q = tid + i * 256;
            int r = q >> 3, c = q & 7;
            const float4* s4 = reinterpret_cast<const float4*>(src + (size_t)r * KK + c * 8);
            float4 v0 = s4[0], v1 = s4[1];
            uint4 w;
            w.x = h2_u32(__floats2half2_rn(v0.x, v0.y));
            w.y = h2_u32(__floats2half2_rn(v0.z, v0.w));
            w.z = h2_u32(__floats2half2_rn(v1.x, v1.y));
            w.w = h2_u32(__floats2half2_rn(v1.z, v1.w));
            int sc = c ^ (r & 7);
            *reinterpret_cast<uint4*>(dst + r * 128 + sc * 16) = w;
        }
    } else {
        int bb = b - NBLOBS_A;
        int tn = bb >> 6, ks = bb & 63;
        const float* src = W + (size_t)ks * 64 * NN + tn * 128;
        char* dst = reinterpret_cast<char*>(g_sh + (size_t)bb * BLOB_ELEMS);
#pragma unroll
        for (int i = 0; i < 8; ++i) {
            int f = tid + i * 256;          // float4 idx, 0..2047 (64 rows x 32)
            int row = f >> 5, c4 = f & 31;
            float4 v = reinterpret_cast<const float4*>(src + (size_t)row * NN)[c4];
            t[row][c4 * 4 + 0] = v.x;
            t[row][c4 * 4 + 1] = v.y;
            t[row][c4 * 4 + 2] = v.z;
            t[row][c4 * 4 + 3] = v.w;
        }
        __syncthreads();
#pragma unroll
        for (int i = 0; i < 4; ++i) {          // 1024 chunks / 256 threads
            int q = tid + i * 256;
            int n = q >> 3, c = q & 7;
            union { __half h[8]; uint4 u; } w;
#pragma unroll
            for (int j = 0; j < 8; ++j) {
                float v = t[c * 8 + j][n];
                float s = (v > 0.f) ? 1.f : ((v < 0.f) ? -1.f : 0.f);
                w.h[j] = __float2half(s);
            }
            int sc = c ^ (n & 7);
            *reinterpret_cast<uint4*>(dst + n * 128 + sc * 16) = w.u;
        }
    }
}

// ---------------------------------------------------------------------------
// GEMM: 128x128 CTA tile, warps 0-3 compute (2x2, 64x64), warp 4 = producer
// ---------------------------------------------------------------------------
__global__ __launch_bounds__(NTHREADS, 2) __cluster_dims__(1, 1, 1)
void gemm_kernel(float* __restrict__ out) {
    extern __shared__ char smem[];
    const uint32_t sbase = smem_u32(smem);
    const uint32_t fullB  = sbase;          // full[3]  at +0,+8,+16
    const uint32_t emptyB = sbase + 24;     // empty[3] at +24,+32,+40
    const uint32_t tiles = sbase + SMEM_TILES_OFF;

    const int tid = threadIdx.x;
    const int wid = tid >> 5;
    const int lane = tid & 31;

    const int TILES_N = NN / TN;   // 32
    const int GROUP_M = 8;
    int bid = blockIdx.x;
    int group = bid / (GROUP_M * TILES_N);
    int rem = bid % (GROUP_M * TILES_N);
    int pm = group * GROUP_M + (rem % GROUP_M);
    int pn = rem / GROUP_M;
    const int m0 = pm * TM;
    const int n0 = pn * TN;

    const __half* blobA = g_xh + (size_t)(pm * 64) * BLOB_ELEMS;
    const __half* blobB = g_sh + (size_t)(pn * 64) * BLOB_ELEMS;

    if (tid == 0) {
#pragma unroll
        for (int s = 0; s < NSTAGE; ++s) {
            MBARRIER_INIT(fullB + 8 * s, 1);
            MBARRIER_INIT(emptyB + 8 * s, 4);       // one arrive per consumer warp
        }
        FENCE_PROXY_ASYNC();
    }
    __syncthreads();        // barrier inits visible to all warps

    if (wid == 4) {
        // =================== dedicated producer warp ===================
        if (lane == 0) {
            // prologue: stages 0 and 1
#pragma unroll
            for (int s = 0; s < 2; ++s) {
                uint32_t bar = fullB + 8 * s;
                MBARRIER_EXPECT_TX(bar, STAGE_BYTES);
                CP_BULK(tiles + s * STAGE_BYTES,
                        blobA + (size_t)s * BLOB_ELEMS, BLOB_BYTES, bar);
                CP_BULK(tiles + s * STAGE_BYTES + BLOB_BYTES,
                        blobB + (size_t)s * BLOB_ELEMS, BLOB_BYTES, bar);
            }
            int es = 0, eph = 0;
            for (int it = 0; it + 2 < NK; ++it) {
                int sn = (it + 2) % NSTAGE;
                if (it >= 1) {
                    MBARRIER_WAIT_PARITY(emptyB + 8 * sn, eph);
                    if (++es == NSTAGE) { es = 0; eph ^= 1; }
                }
                uint32_t bar = fullB + 8 * sn;
                MBARRIER_EXPECT_TX(bar, STAGE_BYTES);
                CP_BULK(tiles + sn * STAGE_BYTES,
                        blobA + (size_t)(it + 2) * BLOB_ELEMS, BLOB_BYTES, bar);
                CP_BULK(tiles + sn * STAGE_BYTES + BLOB_BYTES,
                        blobB + (size_t)(it + 2) * BLOB_ELEMS, BLOB_BYTES, bar);
            }
        }
        return;
    }

    // ===================== consumer warps 0-3 =====================
    const int wm = wid & 1;
    const int wn = wid >> 1;
    const int a_row_base = wm * 64 + (lane & 15);
    const int a_hi = lane >> 4;
    const int b_n_base = wn * 64 + (lane & 7) + ((lane >> 4) << 3);
    const int b_hi = (lane >> 3) & 1;

    float acc[4][8][4];
#pragma unroll
    for (int mt = 0; mt < 4; ++mt)
#pragma unroll
        for (int nf = 0; nf < 8; ++nf)
#pragma unroll
            for (int v = 0; v < 4; ++v) acc[mt][nf][v] = 0.f;

    int s_cur = 0, ph = 0;

    for (int it = 0; it < NK; ++it) {
        MBARRIER_WAIT_PARITY(fullB + 8 * s_cur, ph);

        const uint32_t sa = tiles + s_cur * STAGE_BYTES;
        const uint32_t sb = sa + BLOB_BYTES;

#pragma unroll
        for (int ks = 0; ks < 4; ++ks) {
            uint32_t a[4][4], b[4][4];
#pragma unroll
            for (int mt = 0; mt < 4; ++mt) {
                int row = a_row_base + mt * 16;
                int ch = ks * 2 + a_hi;
                ldsm4(a[mt], sa + row * 128 + ((ch ^ (row & 7)) << 4));
            }
#pragma unroll
            for (int bq = 0; bq < 4; ++bq) {
                int n = b_n_base + bq * 16;
                int ch = ks * 2 + b_hi;
                ldsm4(b[bq], sb + n * 128 + ((ch ^ (n & 7)) << 4));
            }
#pragma unroll
            for (int mt = 0; mt < 4; ++mt)
#pragma unroll
                for (int nf = 0; nf < 8; ++nf)
                    mma16816(acc[mt][nf], a[mt], &b[nf >> 1][(nf & 1) * 2]);
        }

        __syncwarp();
        if (lane == 0) MBARRIER_ARRIVE(emptyB + 8 * s_cur);
        if (++s_cur == NSTAGE) { s_cur = 0; ph ^= 1; }
    }

    // epilogue
#pragma unroll
    for (int mt = 0; mt < 4; ++mt) {
        int r0 = m0 + wm * 64 + mt * 16 + (lane >> 2);
#pragma unroll
        for (int nf = 0; nf < 8; ++nf) {
            int c0 = n0 + wn * 64 + nf * 8 + (lane & 3) * 2;
            float2 v0 = make_float2(acc[mt][nf][0], acc[mt][nf][1]);
            float2 v1 = make_float2(acc[mt][nf][2], acc[mt][nf][3]);
            *reinterpret_cast<float2*>(out + (size_t)r0 * NN + c0) = v0;
            *reinterpret_cast<float2*>(out + (size_t)(r0 + 8) * NN + c0) = v1;
        }
    }
}

// ---------------------------------------------------------------------------
extern "C" void kernel_launch(void* const* d_in, const int* in_sizes, int n_in,
                              void* d_out, int out_size) {
    const float* x;
    const float* W;
    if (in_sizes[0] == MM * KK) {
        x = (const float*)d_in[0];
        W = (const float*)d_in[1];
    } else {
        x = (const float*)d_in[1];
        W = (const float*)d_in[0];
    }

    k_conv<<<NBLOBS_A + NBLOBS_B, 256>>>(x, W);

    cudaFuncSetAttribute(gemm_kernel, cudaFuncAttributeMaxDynamicSharedMemorySize, SMEM_TOTAL);
    int n_tiles = (MM / TM) * (NN / TN);   // 2048
    gemm_kernel<<<n_tiles, NTHREADS, SMEM_TOTAL>>>((float*)d_out);
}

// round 17
// speedup vs baseline: 1.1045x; 1.1045x over previous
#include <cuda_runtime.h>
#include <cuda_fp16.h>
#include <cstdint>

// ============================================================================
// y[8192,4096] = x[8192,4096] @ sign(W)[4096,4096], fp32 in/out.
// Plain-sm_103 target (no tcgen05). Pipelined HMMA GEMM, 2 CTAs/SM,
// CTA tile 128x128, 4 warps (2x2), warp tile 64x64, TK=64, 3 stages,
// bulk-DMA from pre-swizzled blobs + mbarrier ring.
// R17 (= R14 + distributed producer): stage sn=(it+2)%3 is re-armed by warp
// sn (lane 0) — producer overhead hits each warp every 3rd iter instead of
// warp 0 every iter (R16 showed a dedicated 5th warp unbalances SMSPs).
// Empty-waits use relaxed try_wait (post-wait ops are async-proxy only).
// ============================================================================

#define MM 8192
#define NN 4096
#define KK 4096

#define TM 128
#define TN 128
#define TK 64
#define NSTAGE 3
#define NK (KK / TK)               // 64

#define BLOB_BYTES 16384           // one 128x64 fp16 tile, swizzled
#define BLOB_ELEMS 8192
#define STAGE_BYTES (2 * BLOB_BYTES)
#define SMEM_TILES_OFF 1024
#define SMEM_TOTAL (SMEM_TILES_OFF + NSTAGE * STAGE_BYTES)   // 99328 -> 2 CTAs/SM

#define NTHREADS 128               // 4 warps

__device__ __align__(1024) __half g_xh[(size_t)MM * KK];   // A blobs
__device__ __align__(1024) __half g_sh[(size_t)NN * KK];   // B blobs

// ---------------------------------------------------------------------------
__device__ __forceinline__ uint32_t smem_u32(const void* p) {
    uint32_t a;
    asm("{ .reg .u64 t; cvta.to.shared.u64 t, %1; cvt.u32.u64 %0, t; }"
        : "=r"(a) : "l"(p));
    return a;
}
__device__ __forceinline__ uint32_t h2_u32(__half2 h) {
    return reinterpret_cast<uint32_t&>(h);
}

#define MBARRIER_INIT(addr, count) \
    asm volatile("mbarrier.init.shared.b64 [%0], %1;" \
        :: "r"((uint32_t)(addr)), "r"((uint32_t)(count)) : "memory")
#define MBARRIER_EXPECT_TX(addr, bytes) \
    asm volatile("mbarrier.arrive.expect_tx.shared.b64 _, [%0], %1;" \
        :: "r"((uint32_t)(addr)), "r"((uint32_t)(bytes)) : "memory")
#define MBARRIER_ARRIVE(addr) \
    asm volatile("mbarrier.arrive.shared.b64 _, [%0];" \
        :: "r"((uint32_t)(addr)) : "memory")

#define MBARRIER_WAIT_PARITY(mbar_smem_addr, phase_parity) do { \
    uint32_t _mbar = (uint32_t)(mbar_smem_addr); \
    uint32_t _parity = (uint32_t)(phase_parity); \
    uint32_t _done; \
    asm volatile( \
        "{\n\t.reg .pred p;\n\t" \
        "mbarrier.try_wait.parity.acquire.cta.shared::cta.b64 p, [%1], %2;\n\t" \
        "selp.b32 %0, 1, 0, p;\n\t}" \
        : "=r"(_done) : "r"(_mbar), "r"(_parity) : "memory"); \
    if (!_done) { \
        asm volatile( \
            "{\n\t.reg .pred P1;\n\t" \
            "WAIT_LOOP_%=:\n\t" \
            "mbarrier.try_wait.parity.acquire.cta.shared::cta.b64 P1, [%0], %1, 0x989680;\n\t" \
            "@P1 bra.uni WAIT_DONE_%=;\n\t" \
            "bra.uni WAIT_LOOP_%=;\n\t" \
            "WAIT_DONE_%=:\n\t}" \
            :: "r"(_mbar), "r"(_parity) : "memory"); \
    } \
} while (0)

#define MBARRIER_WAIT_PARITY_RELAXED(mbar_smem_addr, phase_parity) do { \
    uint32_t _mbar = (uint32_t)(mbar_smem_addr); \
    uint32_t _parity = (uint32_t)(phase_parity); \
    uint32_t _done; \
    asm volatile( \
        "{\n\t.reg .pred p;\n\t" \
        "mbarrier.try_wait.parity.relaxed.cta.shared::cta.b64 p, [%1], %2, 0x989680;\n\t" \
        "selp.b32 %0, 1, 0, p;\n\t}" \
        : "=r"(_done) : "r"(_mbar), "r"(_parity) : "memory"); \
    if (!_done) { \
        asm volatile( \
            "{\n\t.reg .pred P1;\n\t" \
            "WAIT_LOOP_%=:\n\t" \
            "mbarrier.try_wait.parity.relaxed.cta.shared::cta.b64 P1, [%0], %1, 0x989680;\n\t" \
            "@P1 bra.uni WAIT_DONE_%=;\n\t" \
            "bra.uni WAIT_LOOP_%=;\n\t" \
            "WAIT_DONE_%=:\n\t}" \
            :: "r"(_mbar), "r"(_parity) : "memory"); \
    } \
} while (0)

#define FENCE_PROXY_ASYNC() \
    asm volatile("fence.proxy.async.shared::cta;" ::: "memory")
#define CP_BULK(dst, src, bytes, mbar) \
    asm volatile( \
        "cp.async.bulk.shared::cluster.global.mbarrier::complete_tx::bytes " \
        "[%0], [%1], %2, [%3];" \
        :: "r"((uint32_t)(dst)), "l"(src), "r"((uint32_t)(bytes)), \
           "r"((uint32_t)(mbar)) : "memory")

__device__ __forceinline__ void ldsm4(uint32_t* r, uint32_t addr) {
    asm volatile("ldmatrix.sync.aligned.m8n8.x4.shared.b16 {%0,%1,%2,%3}, [%4];"
        : "=r"(r[0]), "=r"(r[1]), "=r"(r[2]), "=r"(r[3]) : "r"(addr));
}
__device__ __forceinline__ void mma16816(float* c, const uint32_t* a, const uint32_t* b) {
    asm volatile(
        "mma.sync.aligned.m16n8k16.row.col.f32.f16.f16.f32 "
        "{%0,%1,%2,%3}, {%4,%5,%6,%7}, {%8,%9}, {%0,%1,%2,%3};"
        : "+f"(c[0]), "+f"(c[1]), "+f"(c[2]), "+f"(c[3])
        : "r"(a[0]), "r"(a[1]), "r"(a[2]), "r"(a[3]), "r"(b[0]), "r"(b[1]));
}

// ---------------------------------------------------------------------------
// x -> fp16 blobs. Block b: tm = b>>6, ks = b&63. 1024 16B-chunks per blob.
// ---------------------------------------------------------------------------
__global__ void k_cvt_x(const float* __restrict__ x, __half* __restrict__ o) {
    int b = blockIdx.x;
    int tm = b >> 6, ks = b & 63;
    const float* src = x + (size_t)tm * 128 * KK + ks * 64;
    char* dst = reinterpret_cast<char*>(o + (size_t)b * BLOB_ELEMS);
    int tid = threadIdx.x;
#pragma unroll
    for (int i = 0; i < 4; ++i) {
        int q = tid + i * 256;
        int r = q >> 3, c = q & 7;
        const float4* s4 = reinterpret_cast<const float4*>(src + (size_t)r * KK + c * 8);
        float4 v0 = s4[0], v1 = s4[1];
        uint4 w;
        w.x = h2_u32(__floats2half2_rn(v0.x, v0.y));
        w.y = h2_u32(__floats2half2_rn(v0.z, v0.w));
        w.z = h2_u32(__floats2half2_rn(v1.x, v1.y));
        w.w = h2_u32(__floats2half2_rn(v1.z, v1.w));
        int sc = c ^ (r & 7);
        *reinterpret_cast<uint4*>(dst + r * 128 + sc * 16) = w;
    }
}

// ---------------------------------------------------------------------------
// sign(W)^T -> fp16 blobs. Block b: tn = b>>6, ks = b&63.
// ---------------------------------------------------------------------------
__global__ void k_sign_t(const float* __restrict__ W, __half* __restrict__ o) {
    __shared__ float t[64][129];
    int b = blockIdx.x;
    int tn = b >> 6, ks = b & 63;
    const float* src = W + (size_t)ks * 64 * NN + tn * 128;
    char* dst = reinterpret_cast<char*>(o + (size_t)b * BLOB_ELEMS);
    int tid = threadIdx.x;
#pragma unroll
    for (int i = 0; i < 8; ++i) {
        int f = tid + i * 256;
        int row = f >> 5, c4 = f & 31;
        float4 v = reinterpret_cast<const float4*>(src + (size_t)row * NN)[c4];
        t[row][c4 * 4 + 0] = v.x;
        t[row][c4 * 4 + 1] = v.y;
        t[row][c4 * 4 + 2] = v.z;
        t[row][c4 * 4 + 3] = v.w;
    }
    __syncthreads();
#pragma unroll
    for (int i = 0; i < 4; ++i) {
        int q = tid + i * 256;
        int n = q >> 3, c = q & 7;
        union { __half h[8]; uint4 u; } w;
#pragma unroll
        for (int j = 0; j < 8; ++j) {
            float v = t[c * 8 + j][n];
            float s = (v > 0.f) ? 1.f : ((v < 0.f) ? -1.f : 0.f);
            w.h[j] = __float2half(s);
        }
        int sc = c ^ (n & 7);
        *reinterpret_cast<uint4*>(dst + n * 128 + sc * 16) = w.u;
    }
}

// ---------------------------------------------------------------------------
// GEMM: 128x128 CTA tile, 4 warps (2x2, 64x64), bulk DMA + distributed ring
// ---------------------------------------------------------------------------
__global__ __launch_bounds__(NTHREADS, 2) __cluster_dims__(1, 1, 1)
void gemm_kernel(float* __restrict__ out) {
    extern __shared__ char smem[];
    const uint32_t sbase = smem_u32(smem);
    const uint32_t fullB  = sbase;          // full[3]
    const uint32_t emptyB = sbase + 24;     // empty[3]
    const uint32_t tiles = sbase + SMEM_TILES_OFF;

    const int tid = threadIdx.x;
    const int wid = tid >> 5;
    const int lane = tid & 31;
    const int wm = wid & 1;
    const int wn = wid >> 1;

    const int TILES_N = NN / TN;   // 32
    const int GROUP_M = 8;
    int bid = blockIdx.x;
    int group = bid / (GROUP_M * TILES_N);
    int rem = bid % (GROUP_M * TILES_N);
    int pm = group * GROUP_M + (rem % GROUP_M);
    int pn = rem / GROUP_M;
    const int m0 = pm * TM;
    const int n0 = pn * TN;

    const __half* blobA = g_xh + (size_t)(pm * 64) * BLOB_ELEMS;
    const __half* blobB = g_sh + (size_t)(pn * 64) * BLOB_ELEMS;

    if (tid == 0) {
#pragma unroll
        for (int s = 0; s < NSTAGE; ++s) {
            MBARRIER_INIT(fullB + 8 * s, 1);
            MBARRIER_INIT(emptyB + 8 * s, 4);
        }
        FENCE_PROXY_ASYNC();
    }
    __syncthreads();

    if (tid == 0) {
        // prologue: stages 0 and 1 (g = 0, 1)
#pragma unroll
        for (int s = 0; s < 2; ++s) {
            uint32_t bar = fullB + 8 * s;
            MBARRIER_EXPECT_TX(bar, STAGE_BYTES);
            CP_BULK(tiles + s * STAGE_BYTES,
                    blobA + (size_t)s * BLOB_ELEMS, BLOB_BYTES, bar);
            CP_BULK(tiles + s * STAGE_BYTES + BLOB_BYTES,
                    blobB + (size_t)s * BLOB_ELEMS, BLOB_BYTES, bar);
        }
    }

    const int a_row_base = wm * 64 + (lane & 15);
    const int a_hi = lane >> 4;
    const int b_n_base = wn * 64 + (lane & 7) + ((lane >> 4) << 3);
    const int b_hi = (lane >> 3) & 1;

    float acc[4][8][4];
#pragma unroll
    for (int mt = 0; mt < 4; ++mt)
#pragma unroll
        for (int nf = 0; nf < 8; ++nf)
#pragma unroll
            for (int v = 0; v < 4; ++v) acc[mt][nf][v] = 0.f;

    int s_cur = 0, ph = 0;     // consumer full-wait state
    int my_eph = 0;            // this warp's empty-wait parity (one flip per wait)

    for (int it = 0; it < NK; ++it) {
        // ---- distributed producer: warp sn re-arms stage sn = (it+2)%3 ----
        int gq = it + 2;
        int sn = gq % NSTAGE;
        if (wid == sn && lane == 0 && gq < NK) {
            if (gq >= NSTAGE) {   // not the stage's first fill: wait until drained
                MBARRIER_WAIT_PARITY_RELAXED(emptyB + 8 * sn, my_eph);
                my_eph ^= 1;
            }
            uint32_t bar = fullB + 8 * sn;
            MBARRIER_EXPECT_TX(bar, STAGE_BYTES);
            CP_BULK(tiles + sn * STAGE_BYTES,
                    blobA + (size_t)gq * BLOB_ELEMS, BLOB_BYTES, bar);
            CP_BULK(tiles + sn * STAGE_BYTES + BLOB_BYTES,
                    blobB + (size_t)gq * BLOB_ELEMS, BLOB_BYTES, bar);
        }

        // ---- consumer: wait own stage, compute ----
        MBARRIER_WAIT_PARITY(fullB + 8 * s_cur, ph);

        const uint32_t sa = tiles + s_cur * STAGE_BYTES;
        const uint32_t sb = sa + BLOB_BYTES;

#pragma unroll
        for (int ks = 0; ks < 4; ++ks) {
            uint32_t a[4][4], b[4][4];
#pragma unroll
            for (int mt = 0; mt < 4; ++mt) {
                int row = a_row_base + mt * 16;
                int ch = ks * 2 + a_hi;
                ldsm4(a[mt], sa + row * 128 + ((ch ^ (row & 7)) << 4));
            }
#pragma unroll
            for (int bq = 0; bq < 4; ++bq) {
                int n = b_n_base + bq * 16;
                int ch = ks * 2 + b_hi;
                ldsm4(b[bq], sb + n * 128 + ((ch ^ (n & 7)) << 4));
            }
#pragma unroll
            for (int mt = 0; mt < 4; ++mt)
#pragma unroll
                for (int nf = 0; nf < 8; ++nf)
                    mma16816(acc[mt][nf], a[mt], &b[nf >> 1][(nf & 1) * 2]);
        }

        __syncwarp();
        if (lane == 0) MBARRIER_ARRIVE(emptyB + 8 * s_cur);
        if (++s_cur == NSTAGE) { s_cur = 0; ph ^= 1; }
    }

    // epilogue
#pragma unroll
    for (int mt = 0; mt < 4; ++mt) {
        int r0 = m0 + wm * 64 + mt * 16 + (lane >> 2);
#pragma unroll
        for (int nf = 0; nf < 8; ++nf) {
            int c0 = n0 + wn * 64 + nf * 8 + (lane & 3) * 2;
            float2 v0 = make_float2(acc[mt][nf][0], acc[mt][nf][1]);
            float2 v1 = make_float2(acc[mt][nf][2], acc[mt][nf][3]);
            *reinterpret_cast<float2*>(out + (size_t)r0 * NN + c0) = v0;
            *reinterpret_cast<float2*>(out + (size_t)(r0 + 8) * NN + c0) = v1;
        }
    }
}

// ---------------------------------------------------------------------------
extern "C" void kernel_launch(void* const* d_in, const int* in_sizes, int n_in,
                              void* d_out, int out_size) {
    const float* x;
    const float* W;
    if (in_sizes[0] == MM * KK) {
        x = (const float*)d_in[0];
        W = (const float*)d_in[1];
    } else {
        x = (const float*)d_in[1];
        W = (const float*)d_in[0];
    }

    void* xh_ptr = nullptr;
    void* sh_ptr = nullptr;
    cudaGetSymbolAddress(&xh_ptr, g_xh);
    cudaGetSymbolAddress(&sh_ptr, g_sh);

    k_cvt_x<<<(MM / 128) * (KK / 64), 256>>>(x, (__half*)xh_ptr);      // 4096 blocks
    k_sign_t<<<(NN / 128) * (KK / 64), 256>>>(W, (__half*)sh_ptr);     // 2048 blocks

    cudaFuncSetAttribute(gemm_kernel, cudaFuncAttributeMaxDynamicSharedMemorySize, SMEM_TOTAL);
    int n_tiles = (MM / TM) * (NN / TN);   // 2048
    gemm_kernel<<<n_tiles, NTHREADS, SMEM_TOTAL>>>((float*)d_out);
}